// round 1
// baseline (speedup 1.0000x reference)
#include <cuda_runtime.h>

// Problem constants
#define NB 8
#define NS 1024
#define DM 768
#define NH 12
#define DH 64
#define MROWS (NB * NS)                 // 8192
#define OUT_ELEMS (MROWS * DM)          // 6291456
#define ATTN_ELEMS (NB * NH * NS * NS)  // 100663296

// Scratch (device globals — allocation-free per harness rules)
__device__ float g_q[OUT_ELEMS];     // Q proj [B,H,S,DH]; reused later as pre-LN buffer
__device__ float g_k[OUT_ELEMS];     // K proj [B,H,S,DH]
__device__ float g_v[OUT_ELEMS];     // V proj [B,H,S,DH]
__device__ float g_ctx[OUT_ELEMS];   // context [B,S,H*DH]
__device__ float g_attn[ATTN_ELEMS]; // fallback attn buffer if d_out lacks room

// ---------------------------------------------------------------------------
// QKV projection: out = X[8192,768] @ W[768,768] + b, scattered to [B,H,S,64]
// 64x64 tile, 16x16 threads, 4x4 per thread, BK=16
// ---------------------------------------------------------------------------
__global__ void proj_kernel(const float* __restrict__ X, const float* __restrict__ W,
                            const float* __restrict__ bias, float* __restrict__ out)
{
    __shared__ __align__(16) float As[16][68];
    __shared__ __align__(16) float Bs[16][64];
    const int row0 = blockIdx.y * 64;
    const int col0 = blockIdx.x * 64;
    const int tx = threadIdx.x, ty = threadIdx.y;
    const int t = ty * 16 + tx;
    float acc[4][4] = {};

    for (int k0 = 0; k0 < DM; k0 += 16) {
#pragma unroll
        for (int l = 0; l < 4; l++) {
            int idx = t + l * 256;
            As[idx & 15][idx >> 4] = X[(size_t)(row0 + (idx >> 4)) * DM + k0 + (idx & 15)];
        }
#pragma unroll
        for (int l = 0; l < 4; l++) {
            int idx = t + l * 256;
            Bs[idx >> 6][idx & 63] = W[(size_t)(k0 + (idx >> 6)) * DM + col0 + (idx & 63)];
        }
        __syncthreads();
#pragma unroll
        for (int kk = 0; kk < 16; kk++) {
            float4 a = *(const float4*)&As[kk][ty * 4];
            float4 b = *(const float4*)&Bs[kk][tx * 4];
            float av[4] = {a.x, a.y, a.z, a.w};
            float bv[4] = {b.x, b.y, b.z, b.w};
#pragma unroll
            for (int i = 0; i < 4; i++)
#pragma unroll
                for (int j = 0; j < 4; j++)
                    acc[i][j] += av[i] * bv[j];
        }
        __syncthreads();
    }
#pragma unroll
    for (int i = 0; i < 4; i++) {
        int r = row0 + ty * 4 + i;
        int bb = r >> 10, s = r & 1023;
#pragma unroll
        for (int j = 0; j < 4; j++) {
            int c = col0 + tx * 4 + j;
            int h = c >> 6, d = c & 63;
            out[(((size_t)bb * NH + h) * NS + s) * DH + d] = acc[i][j] + bias[c];
        }
    }
}

// ---------------------------------------------------------------------------
// scores = (q @ k^T) / 8, with mask fill -1e9. One (b,h) per blockIdx.z.
// 64x64 output tile, full K=64 in smem.
// ---------------------------------------------------------------------------
__global__ void scores_kernel(const unsigned char* __restrict__ mask, float* __restrict__ attn)
{
    __shared__ __align__(16) float Qs[64][68];  // [d][m]
    __shared__ __align__(16) float Ks[64][68];  // [d][n]
    const int bh = blockIdx.z;
    const int b = bh / NH;
    const float* qp = g_q + (size_t)bh * NS * DH;
    const float* kp = g_k + (size_t)bh * NS * DH;
    const int m0 = blockIdx.y * 64, n0 = blockIdx.x * 64;
    const int tx = threadIdx.x, ty = threadIdx.y;
    const int t = ty * 16 + tx;

#pragma unroll
    for (int l = 0; l < 16; l++) {
        int idx = t + l * 256;
        int s = idx >> 6, d = idx & 63;
        Qs[d][s] = qp[(size_t)(m0 + s) * DH + d];
        Ks[d][s] = kp[(size_t)(n0 + s) * DH + d];
    }
    __syncthreads();

    float acc[4][4] = {};
#pragma unroll 8
    for (int d = 0; d < 64; d++) {
        float4 a = *(const float4*)&Qs[d][ty * 4];
        float4 bb4 = *(const float4*)&Ks[d][tx * 4];
        float av[4] = {a.x, a.y, a.z, a.w};
        float bv[4] = {bb4.x, bb4.y, bb4.z, bb4.w};
#pragma unroll
        for (int i = 0; i < 4; i++)
#pragma unroll
            for (int j = 0; j < 4; j++)
                acc[i][j] += av[i] * bv[j];
    }

#pragma unroll
    for (int i = 0; i < 4; i++) {
        int sq = m0 + ty * 4 + i;
#pragma unroll
        for (int j = 0; j < 4; j++) {
            int sk = n0 + tx * 4 + j;
            float v = acc[i][j] * 0.125f;
            if (mask[((size_t)b * NS + sq) * NS + sk]) v = -1e9f;
            attn[((size_t)bh * NS + sq) * NS + sk] = v;
        }
    }
}

// ---------------------------------------------------------------------------
// Row softmax in place (row length 1024), one block per row.
// ---------------------------------------------------------------------------
__global__ void softmax_kernel(float* __restrict__ attn)
{
    float* p = attn + (size_t)blockIdx.x * NS;
    const int t = threadIdx.x;
    __shared__ float red[256];

    float x[4];
    float mx = -3.4e38f;
#pragma unroll
    for (int i = 0; i < 4; i++) { x[i] = p[t + i * 256]; mx = fmaxf(mx, x[i]); }
    red[t] = mx; __syncthreads();
    for (int o = 128; o > 0; o >>= 1) { if (t < o) red[t] = fmaxf(red[t], red[t + o]); __syncthreads(); }
    mx = red[0]; __syncthreads();

    float sum = 0.f;
#pragma unroll
    for (int i = 0; i < 4; i++) { x[i] = expf(x[i] - mx); sum += x[i]; }
    red[t] = sum; __syncthreads();
    for (int o = 128; o > 0; o >>= 1) { if (t < o) red[t] += red[t + o]; __syncthreads(); }
    float inv = 1.f / red[0];
#pragma unroll
    for (int i = 0; i < 4; i++) p[t + i * 256] = x[i] * inv;
}

// ---------------------------------------------------------------------------
// context = attn[1024,1024] @ v[1024,64] per (b,h). Writes [B,S,H*DH].
// ---------------------------------------------------------------------------
__global__ void context_kernel(const float* __restrict__ attn)
{
    __shared__ __align__(16) float As[16][68];
    __shared__ __align__(16) float Bs[16][64];
    const int bh = blockIdx.y;
    const int b = bh / NH, h = bh % NH;
    const float* ap = attn + (size_t)bh * NS * NS;
    const float* vp = g_v + (size_t)bh * NS * DH;
    const int m0 = blockIdx.x * 64;
    const int tx = threadIdx.x, ty = threadIdx.y;
    const int t = ty * 16 + tx;
    float acc[4][4] = {};

    for (int k0 = 0; k0 < NS; k0 += 16) {
#pragma unroll
        for (int l = 0; l < 4; l++) {
            int idx = t + l * 256;
            As[idx & 15][idx >> 4] = ap[(size_t)(m0 + (idx >> 4)) * NS + k0 + (idx & 15)];
        }
#pragma unroll
        for (int l = 0; l < 4; l++) {
            int idx = t + l * 256;
            Bs[idx >> 6][idx & 63] = vp[(size_t)(k0 + (idx >> 6)) * DH + (idx & 63)];
        }
        __syncthreads();
#pragma unroll
        for (int kk = 0; kk < 16; kk++) {
            float4 a = *(const float4*)&As[kk][ty * 4];
            float4 bb4 = *(const float4*)&Bs[kk][tx * 4];
            float av[4] = {a.x, a.y, a.z, a.w};
            float bv[4] = {bb4.x, bb4.y, bb4.z, bb4.w};
#pragma unroll
            for (int i = 0; i < 4; i++)
#pragma unroll
                for (int j = 0; j < 4; j++)
                    acc[i][j] += av[i] * bv[j];
        }
        __syncthreads();
    }
#pragma unroll
    for (int i = 0; i < 4; i++) {
        int sq = m0 + ty * 4 + i;
#pragma unroll
        for (int j = 0; j < 4; j++) {
            g_ctx[((size_t)b * NS + sq) * DM + h * DH + tx * 4 + j] = acc[i][j];
        }
    }
}

// ---------------------------------------------------------------------------
// O projection: preln = ctx @ W_O + b_O + residual(Q)
// ---------------------------------------------------------------------------
__global__ void oproj_kernel(const float* __restrict__ Xres, const float* __restrict__ W,
                             const float* __restrict__ bias, float* __restrict__ out)
{
    __shared__ __align__(16) float As[16][68];
    __shared__ __align__(16) float Bs[16][64];
    const int row0 = blockIdx.y * 64;
    const int col0 = blockIdx.x * 64;
    const int tx = threadIdx.x, ty = threadIdx.y;
    const int t = ty * 16 + tx;
    float acc[4][4] = {};

    for (int k0 = 0; k0 < DM; k0 += 16) {
#pragma unroll
        for (int l = 0; l < 4; l++) {
            int idx = t + l * 256;
            As[idx & 15][idx >> 4] = g_ctx[(size_t)(row0 + (idx >> 4)) * DM + k0 + (idx & 15)];
        }
#pragma unroll
        for (int l = 0; l < 4; l++) {
            int idx = t + l * 256;
            Bs[idx >> 6][idx & 63] = W[(size_t)(k0 + (idx >> 6)) * DM + col0 + (idx & 63)];
        }
        __syncthreads();
#pragma unroll
        for (int kk = 0; kk < 16; kk++) {
            float4 a = *(const float4*)&As[kk][ty * 4];
            float4 bb4 = *(const float4*)&Bs[kk][tx * 4];
            float av[4] = {a.x, a.y, a.z, a.w};
            float bv[4] = {bb4.x, bb4.y, bb4.z, bb4.w};
#pragma unroll
            for (int i = 0; i < 4; i++)
#pragma unroll
                for (int j = 0; j < 4; j++)
                    acc[i][j] += av[i] * bv[j];
        }
        __syncthreads();
    }
#pragma unroll
    for (int i = 0; i < 4; i++) {
        int r = row0 + ty * 4 + i;
#pragma unroll
        for (int j = 0; j < 4; j++) {
            int c = col0 + tx * 4 + j;
            out[(size_t)r * DM + c] = acc[i][j] + bias[c] + Xres[(size_t)r * DM + c];
        }
    }
}

// ---------------------------------------------------------------------------
// LayerNorm over last dim (768). One block per row.
// ---------------------------------------------------------------------------
__global__ void ln_kernel(const float* __restrict__ x, const float* __restrict__ gamma,
                          const float* __restrict__ beta, float* __restrict__ out)
{
    const float* p = x + (size_t)blockIdx.x * DM;
    const int t = threadIdx.x;
    __shared__ float red[256];

    float v[3];
    float s = 0.f;
#pragma unroll
    for (int i = 0; i < 3; i++) { v[i] = p[t + i * 256]; s += v[i]; }
    red[t] = s; __syncthreads();
    for (int o = 128; o > 0; o >>= 1) { if (t < o) red[t] += red[t + o]; __syncthreads(); }
    float mean = red[0] * (1.f / DM); __syncthreads();

    float sq = 0.f;
#pragma unroll
    for (int i = 0; i < 3; i++) { float d = v[i] - mean; sq += d * d; }
    red[t] = sq; __syncthreads();
    for (int o = 128; o > 0; o >>= 1) { if (t < o) red[t] += red[t + o]; __syncthreads(); }
    float inv = rsqrtf(red[0] * (1.f / DM) + 1e-5f);

#pragma unroll
    for (int i = 0; i < 3; i++) {
        int c = t + i * 256;
        out[(size_t)blockIdx.x * DM + c] = (v[i] - mean) * inv * gamma[c] + beta[c];
    }
}

// ---------------------------------------------------------------------------
extern "C" void kernel_launch(void* const* d_in, const int* in_sizes, int n_in,
                              void* d_out, int out_size)
{
    const float* Qin  = (const float*)d_in[0];
    const float* Kin  = (const float*)d_in[1];
    const float* Vin  = (const float*)d_in[2];
    const float* WQ   = (const float*)d_in[3];
    const float* bQ   = (const float*)d_in[4];
    const float* WK   = (const float*)d_in[5];
    const float* bK   = (const float*)d_in[6];
    const float* WV   = (const float*)d_in[7];
    const float* bV   = (const float*)d_in[8];
    const float* WO   = (const float*)d_in[9];
    const float* bO   = (const float*)d_in[10];
    const float* lng  = (const float*)d_in[11];
    const float* lnb  = (const float*)d_in[12];
    const unsigned char* mask = (const unsigned char*)d_in[13];

    float* out = (float*)d_out;

    float *q, *k, *v, *attn_scratch;
    cudaGetSymbolAddress((void**)&q, g_q);
    cudaGetSymbolAddress((void**)&k, g_k);
    cudaGetSymbolAddress((void**)&v, g_v);
    cudaGetSymbolAddress((void**)&attn_scratch, g_attn);

    // attn output lives in d_out after `out` if the harness sized it for the tuple
    float* attn = ((long long)out_size >= (long long)OUT_ELEMS + (long long)ATTN_ELEMS)
                      ? (out + OUT_ELEMS) : attn_scratch;

    dim3 blk(16, 16);
    proj_kernel<<<dim3(DM / 64, MROWS / 64), blk>>>(Qin, WQ, bQ, q);
    proj_kernel<<<dim3(DM / 64, MROWS / 64), blk>>>(Kin, WK, bK, k);
    proj_kernel<<<dim3(DM / 64, MROWS / 64), blk>>>(Vin, WV, bV, v);

    scores_kernel<<<dim3(NS / 64, NS / 64, NB * NH), blk>>>(mask, attn);
    softmax_kernel<<<NB * NH * NS, 256>>>(attn);
    context_kernel<<<dim3(NS / 64, NB * NH), blk>>>(attn);

    // O-proj + bias + residual into g_q (q no longer needed), then LayerNorm
    oproj_kernel<<<dim3(DM / 64, MROWS / 64), blk>>>(Qin, WO, bO, q);
    ln_kernel<<<MROWS, 256>>>(q, lng, lnb, out);
}